// round 15
// baseline (speedup 1.0000x reference)
#include <cuda_runtime.h>
#include <cuda_fp16.h>

#define H      64
#define E_PER  300000
#define RTOT   9
#define ETOT   (RTOT * E_PER)
#define NB     64
#define N0     100000
#define N1     20000
#define N2     50000
#define N3     80000
#define NTOT   250000
#define NMAX   100000
#define NDSUM  660000   // sum of Nd over relations

// ---------------- static device scratch ----------------
__device__ float   g_feat0[NTOT * H];
__device__ float   g_feat1[NTOT * H];
__device__ __half2 g_xh[(size_t)NTOT * 32];   // fp16 activated features (per layer)
__device__ float   g_als[RTOT * NMAX];
__device__ float   g_ald[RTOT * NMAX];
__device__ float   g_wsv[2 * RTOT * H];
__device__ float   g_wdv[2 * RTOT * H];
__device__ float   g_pool[NB * 2 * H];
__device__ float   g_cnt[2 * NB];
// compact CSR: entry index = c_DOFF[r] + d ; offsets are global into g_csrc
__device__ int     g_deg[NDSUM];
__device__ int     g_off[NDSUM];
__device__ int     g_cursor[1];
__device__ int     g_csrc[ETOT];
__device__ int     g_epos[ETOT];              // per-edge slot from hist pass

__constant__ int c_ST[9]  = {0, 0, 0, 2, 3, 1, 2, 3, 3};
__constant__ int c_NSZ[4] = {N0, N1, N2, N3};
__constant__ int c_OFF[4] = {0, N0, N0 + N1, N0 + N1 + N2};
__constant__ int c_DOFF[10] = {0, 20000, 70000, 150000, 230000, 310000,
                               410000, 510000, 610000, 660000};
// relations targeting type t, -1 padded
__constant__ int c_TB[4][3] = {{5, 6, 7}, {0, -1, -1}, {1, 8, -1}, {2, 3, 4}};
// cumulative 32-row tile counts per dst type
__constant__ int c_TILE0[5] = {0, 3125, 3750, 5313, 7813};
#define FUSED_BLK 7813
// per-type (relation,side) lists: code = (r<<1)|isDst
__constant__ int c_NSIDE[4]   = {6, 2, 4, 6};
__constant__ int c_SIDE[4][6] = {
    {0*2+0, 1*2+0, 2*2+0, 5*2+1, 6*2+1, 7*2+1},
    {5*2+0, 0*2+1, 0, 0, 0, 0},
    {3*2+0, 6*2+0, 1*2+1, 8*2+1, 0, 0},
    {4*2+0, 7*2+0, 8*2+0, 2*2+1, 3*2+1, 4*2+1},
};

struct XP { const float* x[4]; };
struct EP { const int* s[9]; const int* d[9]; };

// ---------------------------- mma helpers ----------------------------
// fp16 m16n8k16, fp32 accumulate (fp16 mantissa == tf32 mantissa: no extra error)
__device__ __forceinline__ void hmma16(float* c, unsigned a0, unsigned a1,
                                       unsigned a2, unsigned a3,
                                       unsigned b0, unsigned b1) {
    asm volatile(
        "mma.sync.aligned.m16n8k16.row.col.f32.f16.f16.f32 "
        "{%0,%1,%2,%3},{%4,%5,%6,%7},{%8,%9},{%0,%1,%2,%3};"
        : "+f"(c[0]), "+f"(c[1]), "+f"(c[2]), "+f"(c[3])
        : "r"(a0), "r"(a1), "r"(a2), "r"(a3), "r"(b0), "r"(b1));
}

// fp16 row chunk (8 halves) weighted-accumulate into 8 fp32 accumulators
__device__ __forceinline__ void acc_h8(float* acc, float4 q, float pw) {
    __half2* h = (__half2*)&q;
    #pragma unroll
    for (int j = 0; j < 4; j++) {
        float2 f = __half22float2(h[j]);
        acc[2 * j]     += pw * f.x;
        acc[2 * j + 1] += pw * f.y;
    }
}

// ------------------------------- CSR build (once) -------------------------------
__global__ void csr_zero() {
    int i = blockIdx.x * blockDim.x + threadIdx.x;
    if (i < NDSUM) g_deg[i] = 0;
    if (i == 0)    g_cursor[0] = 0;
    if (i < NB * 2 * H) g_pool[i] = 0.f;       // fused pool_zero
    if (i < 2 * NB)     g_cnt[i]  = 0.f;
}

// histogram; also records each edge's slot within its dst list
__global__ void csr_hist(EP ep) {
    int idx = blockIdx.x * blockDim.x + threadIdx.x;
    if (idx >= ETOT) return;
    int r = idx / E_PER, e = idx - r * E_PER;
    int gi = c_DOFF[r] + __ldg(&ep.d[r][e]);
    g_epos[idx] = atomicAdd(&g_deg[gi], 1);
}

// block-aggregated global offset assignment (one cursor; list order irrelevant)
__global__ void csr_assign() {
    int i = blockIdx.x * 256 + threadIdx.x;
    int lane = threadIdx.x & 31, w = threadIdx.x >> 5;
    __shared__ int sm[8];
    int deg = (i < NDSUM) ? g_deg[i] : 0;
    int v = deg;
    #pragma unroll
    for (int o = 1; o < 32; o <<= 1) {
        int t = __shfl_up_sync(0xffffffffu, v, o);
        if (lane >= o) v += t;
    }
    if (lane == 31) sm[w] = v;
    __syncthreads();
    if (threadIdx.x == 0) {
        int tmp[8];
        int s = 0;
        #pragma unroll
        for (int k = 0; k < 8; k++) { tmp[k] = s; s += sm[k]; }
        int b = atomicAdd(&g_cursor[0], s);
        #pragma unroll
        for (int k = 0; k < 8; k++) sm[k] = tmp[k] + b;
    }
    __syncthreads();
    if (i < NDSUM) g_off[i] = sm[w] + v - deg;
}

// atomic-free fill using precomputed slots
__global__ void csr_fill(EP ep) {
    int idx = blockIdx.x * blockDim.x + threadIdx.x;
    if (idx >= ETOT) return;
    int r = idx / E_PER, e = idx - r * E_PER;
    int gi = c_DOFF[r] + __ldg(&ep.d[r][e]);
    g_csrc[g_off[gi] + g_epos[idx]] = __ldg(&ep.s[r][e]);
}

// ---------------------------------- per-layer -----------------------------------

// both layers: block rl in [0,18): wsv[rl][k] = sum_j Wsrc[rl][k][j]*asrc[rl][j]
__global__ void prep(const float* __restrict__ Ws, const float* __restrict__ as_,
                     const float* __restrict__ Wd, const float* __restrict__ ad_) {
    int rl = blockIdx.x, t = threadIdx.x;
    const float* W; const float* a; float* o; int k;
    if (t < 64) { W = Ws + rl * 4096; a = as_ + rl * 64; o = g_wsv + rl * 64; k = t; }
    else        { W = Wd + rl * 4096; a = ad_ + rl * 64; o = g_wdv + rl * 64; k = t - 64; }
    float s = 0.f;
    #pragma unroll
    for (int j = 0; j < 64; j++) s += W[k * 64 + j] * a[j];
    o[k] = s;
}

// 8-lane group per node (4 nodes/warp): attention logits via per-type side table,
// plus fp16 conversion of the activated feature row into g_xh.
__global__ void __launch_bounds__(256) alpha_all(XP xp, int use_feat, int wbase) {
    int tid = threadIdx.x, warp = tid >> 5, lane = tid & 31;
    int grp = lane >> 3, lg = lane & 7;
    unsigned gmask = 0xFFu << (grp * 8);
    int gw = blockIdx.x * 32 + warp * 4 + grp;
    if (gw >= NTOT) return;                     // uniform within each 8-lane group
    int t = (gw < N0) ? 0 : (gw < N0 + N1) ? 1 : (gw < N0 + N1 + N2) ? 2 : 3;
    int li = gw - c_OFF[t];
    const float4* x4 = (const float4*)(use_feat ? (g_feat0 + (size_t)c_OFF[t] * H)
                                                : xp.x[t]);
    float4 q0 = x4[(size_t)li * 16 + lg * 2];
    float4 q1 = x4[(size_t)li * 16 + lg * 2 + 1];
    if (use_feat) {
        q0.x = fmaxf(q0.x, 0.f); q0.y = fmaxf(q0.y, 0.f);
        q0.z = fmaxf(q0.z, 0.f); q0.w = fmaxf(q0.w, 0.f);
        q1.x = fmaxf(q1.x, 0.f); q1.y = fmaxf(q1.y, 0.f);
        q1.z = fmaxf(q1.z, 0.f); q1.w = fmaxf(q1.w, 0.f);
    }
    // fp16 row cache: lane lg covers halves [lg*8, lg*8+8) = one 16B store
    __half2 hh[4];
    hh[0] = __floats2half2_rn(q0.x, q0.y);
    hh[1] = __floats2half2_rn(q0.z, q0.w);
    hh[2] = __floats2half2_rn(q1.x, q1.y);
    hh[3] = __floats2half2_rn(q1.z, q1.w);
    *(float4*)&g_xh[(size_t)gw * 32 + lg * 4] = *(float4*)hh;

    int ns = c_NSIDE[t];
    for (int i = 0; i < ns; i++) {
        int code = c_SIDE[t][i];
        int r = code >> 1;
        const float* w = ((code & 1) ? g_wdv : g_wsv) + wbase + r * 64 + lg * 8;
        float4 w0 = *(const float4*)w;
        float4 w1 = *(const float4*)(w + 4);
        float s = q0.x * w0.x + q0.y * w0.y + q0.z * w0.z + q0.w * w0.w
                + q1.x * w1.x + q1.y * w1.y + q1.z * w1.z + q1.w * w1.w;
        #pragma unroll
        for (int o = 4; o; o >>= 1) s += __shfl_xor_sync(gmask, s, o, 8);
        if (lg == 0) ((code & 1) ? g_ald : g_als)[r * NMAX + li] = s;
    }
}

// Fused gather + fp16 HMMA GEMM per dst-type tile of 32 rows.
// sG (gathered rows) and sWT (weights, transposed [n][k]) stored as fp16 in smem.
__global__ void __launch_bounds__(256, 5) fused(const float* __restrict__ Ws_l,
                                                const float* __restrict__ bias_l,
                                                int outbuf) {
    __shared__ __half sG[32 * 88];    // [row][k], stride 88 halves (176B, 16B-mult)
    __shared__ __half sWT[64 * 88];   // [n][k], transposed weights
    __shared__ float sBias[64];
    int bx = blockIdx.x;
    int t = 0;
    #pragma unroll
    for (int i = 1; i < 4; i++) if (bx >= c_TILE0[i]) t = i;
    int row0 = (bx - c_TILE0[t]) * 32;
    int Nd = c_NSZ[t];
    int tid = threadIdx.x, warp = tid >> 5, lane = tid & 31;
    int grp = lane >> 3, lg = lane & 7;
    unsigned gmask = 0xFFu << (grp * 8);
    int nl = warp * 4 + grp;
    int d = row0 + nl;
    bool act = d < Nd;

    if (tid < 64) {
        float s = 0.f;
        #pragma unroll
        for (int i = 0; i < 3; i++) {
            int r = c_TB[t][i];
            if (r >= 0) s += bias_l[r * 64 + tid];
        }
        sBias[tid] = s;
    }

    // 8-warp MMA layout: warp -> 16-row half x 16-col quarter
    int mrow = (warp & 1) * 16;
    int nh = warp >> 1;                 // 0..3
    int gid = lane >> 2, tig = lane & 3;
    float acc[2][4];
    #pragma unroll
    for (int n = 0; n < 2; n++)
        #pragma unroll
        for (int j = 0; j < 4; j++) acc[n][j] = 0.f;

    #pragma unroll
    for (int ri = 0; ri < 3; ri++) {
        int r = c_TB[t][ri];
        if (r < 0) break;
        int st = c_ST[r];
        const char* xb = (const char*)(g_xh + (size_t)c_OFF[st] * 32);
        __syncthreads();               // previous MMA done with sG/sWT

        // W[k][n] -> sWT[n][k] as fp16 (transpose on store)
        const float4* W4 = (const float4*)(Ws_l + (size_t)r * 4096);
        #pragma unroll
        for (int i = 0; i < 4; i++) {
            int idx = tid + i * 256;
            int kk = idx >> 4, n4 = idx & 15;
            float4 v = W4[idx];
            sWT[(n4 * 4 + 0) * 88 + kk] = __float2half(v.x);
            sWT[(n4 * 4 + 1) * 88 + kk] = __float2half(v.y);
            sWT[(n4 * 4 + 2) * 88 + kk] = __float2half(v.z);
            sWT[(n4 * 4 + 3) * 88 + kk] = __float2half(v.w);
        }

        float ald = 0.f; int beg = 0, deg = 0;
        if (act) {
            int gi = c_DOFF[r] + d;
            ald = __ldg(&g_ald[(size_t)r * NMAX + d]);
            beg = __ldg(&g_off[gi]);
            deg = __ldg(&g_deg[gi]);
        }
        const int* sl = g_csrc + beg;
        const float* als = g_als + (size_t)r * NMAX;
        unsigned loff = (unsigned)(lg * 16);

        float accA[8] = {0.f, 0.f, 0.f, 0.f, 0.f, 0.f, 0.f, 0.f};
        float accB[8] = {0.f, 0.f, 0.f, 0.f, 0.f, 0.f, 0.f, 0.f};
        float zl = 0.f;
        for (int base = 0; base < deg; base += 8) {
            int n = min(8, deg - base);
            int sidx = 0; float p = 0.f;
            if (lg < n) {
                sidx = __ldg(&sl[base + lg]);
                float sc = __ldg(&als[sidx]) + ald;
                sc = sc > 0.f ? sc : 0.2f * sc;
                p = __expf(sc);
            }
            zl += p;
            int i = 0;
            for (; i + 2 <= n; i += 2) {
                int   s0 = __shfl_sync(gmask, sidx, i,     8);
                int   s1 = __shfl_sync(gmask, sidx, i + 1, 8);
                float p0 = __shfl_sync(gmask, p,    i,     8);
                float p1 = __shfl_sync(gmask, p,    i + 1, 8);
                float4 q0 = *(const float4*)(xb + (((unsigned)s0 << 7) + loff));
                float4 q1 = *(const float4*)(xb + (((unsigned)s1 << 7) + loff));
                acc_h8(accA, q0, p0);
                acc_h8(accB, q1, p1);
            }
            if (i < n) {
                int   s0 = __shfl_sync(gmask, sidx, i, 8);
                float p0 = __shfl_sync(gmask, p,    i, 8);
                float4 q0 = *(const float4*)(xb + (((unsigned)s0 << 7) + loff));
                acc_h8(accA, q0, p0);
            }
        }
        #pragma unroll
        for (int o = 4; o; o >>= 1) zl += __shfl_xor_sync(gmask, zl, o, 8);
        float inv = act ? __fdividef(1.f, zl + 1e-16f) : 0.f;
        // write gathered row as fp16: lane covers halves [lg*8, lg*8+8) = 16B store
        __half2 hv[4];
        #pragma unroll
        for (int j = 0; j < 4; j++)
            hv[j] = __floats2half2_rn((accA[2 * j]     + accB[2 * j])     * inv,
                                      (accA[2 * j + 1] + accB[2 * j + 1]) * inv);
        *(float4*)&sG[nl * 88 + lg * 8] = *(float4*)hv;
        __syncthreads();

        // ---- fp16 m16n8k16 MMA on all 8 warps: acc += sG @ W_r (16x16 per warp) ----
        #pragma unroll
        for (int k0 = 0; k0 < 4; k0++) {
            int kb = k0 * 16 + 2 * tig;
            unsigned a0 = *(const unsigned*)&sG[(mrow + gid)     * 88 + kb];
            unsigned a1 = *(const unsigned*)&sG[(mrow + gid + 8) * 88 + kb];
            unsigned a2 = *(const unsigned*)&sG[(mrow + gid)     * 88 + kb + 8];
            unsigned a3 = *(const unsigned*)&sG[(mrow + gid + 8) * 88 + kb + 8];
            #pragma unroll
            for (int n0 = 0; n0 < 2; n0++) {
                int nc = nh * 16 + n0 * 8 + gid;
                unsigned b0 = *(const unsigned*)&sWT[nc * 88 + kb];
                unsigned b1 = *(const unsigned*)&sWT[nc * 88 + kb + 8];
                hmma16(acc[n0], a0, a1, a2, a3, b0, b1);
            }
        }
    }

    // epilogue: acc + bias -> fp32 feature rows
    float* fb = ((outbuf == 0) ? g_feat0 : g_feat1) + (size_t)c_OFF[t] * H;
    int rr0 = row0 + mrow + gid;
    int rr1 = rr0 + 8;
    #pragma unroll
    for (int n0 = 0; n0 < 2; n0++) {
        int cc = nh * 16 + n0 * 8 + 2 * tig;
        float b0 = sBias[cc], b1 = sBias[cc + 1];
        if (rr0 < Nd) {
            float2* p = (float2*)(fb + (size_t)rr0 * H + cc);
            *p = make_float2(acc[n0][0] + b0, acc[n0][1] + b1);
        }
        if (rr1 < Nd) {
            float2* p = (float2*)(fb + (size_t)rr1 * H + cc);
            *p = make_float2(acc[n0][2] + b0, acc[n0][3] + b1);
        }
    }
}

// ---------------------------------- pooling -------------------------------------
#define NPW 16
__global__ void pool_kernel(const int* __restrict__ bvar, const int* __restrict__ bcon) {
    int warp = threadIdx.x >> 5, lane = threadIdx.x & 31;
    int gw = blockIdx.x * 8 + warp;
    const int nvw = (N0 + NPW - 1) / NPW;
    const int ncw = (N3 + NPW - 1) / NPW;
    if (gw < nvw) {
        int i0 = gw * NPW, i1 = min(N0, i0 + NPW);
        float a0 = 0.f, a1 = 0.f, cnt = 0.f;
        int curb = __ldg(&bvar[i0]);
        for (int i = i0; i < i1; i++) {
            int b = __ldg(&bvar[i]);
            if (b != curb) {
                atomicAdd(&g_pool[curb * 128 + lane], a0);
                atomicAdd(&g_pool[curb * 128 + 32 + lane], a1);
                if (lane == 0) atomicAdd(&g_cnt[curb], cnt);
                a0 = a1 = 0.f; cnt = 0.f; curb = b;
            }
            size_t base = (size_t)i * H;
            a0 += fmaxf(g_feat1[base + lane], 0.f);
            a1 += fmaxf(g_feat1[base + 32 + lane], 0.f);
            cnt += 1.f;
        }
        atomicAdd(&g_pool[curb * 128 + lane], a0);
        atomicAdd(&g_pool[curb * 128 + 32 + lane], a1);
        if (lane == 0) atomicAdd(&g_cnt[curb], cnt);
    } else if (gw < nvw + ncw) {
        int gj = gw - nvw;
        const float* xc = g_feat1 + (size_t)(N0 + N1 + N2) * H;
        int i0 = gj * NPW, i1 = min(N3, i0 + NPW);
        float a0 = 0.f, a1 = 0.f, cnt = 0.f;
        int curb = __ldg(&bcon[i0]);
        for (int i = i0; i < i1; i++) {
            int b = __ldg(&bcon[i]);
            if (b != curb) {
                atomicAdd(&g_pool[curb * 128 + 64 + lane], a0);
                atomicAdd(&g_pool[curb * 128 + 96 + lane], a1);
                if (lane == 0) atomicAdd(&g_cnt[NB + curb], cnt);
                a0 = a1 = 0.f; cnt = 0.f; curb = b;
            }
            size_t base = (size_t)i * H;
            a0 += fmaxf(xc[base + lane], 0.f);
            a1 += fmaxf(xc[base + 32 + lane], 0.f);
            cnt += 1.f;
        }
        atomicAdd(&g_pool[curb * 128 + 64 + lane], a0);
        atomicAdd(&g_pool[curb * 128 + 96 + lane], a1);
        if (lane == 0) atomicAdd(&g_cnt[NB + curb], cnt);
    }
}

__global__ void final_kernel(const float* __restrict__ lw, const float* __restrict__ lb,
                             float* __restrict__ out) {
    int t = threadIdx.x;
    if (t >= 128) return;
    int b = t >> 1, o = t & 1;
    float cv = fmaxf(g_cnt[b], 1.f);
    float cc = fmaxf(g_cnt[NB + b], 1.f);
    float s = lb[o];
    #pragma unroll
    for (int j = 0; j < H; j++) {
        s += (g_pool[b * 128 + j]      / cv) * lw[o * 128 + j];
        s += (g_pool[b * 128 + 64 + j] / cc) * lw[o * 128 + 64 + j];
    }
    out[b * 2 + o] = s;
}

// ---------------------------------- launcher -------------------------------------
extern "C" void kernel_launch(void* const* d_in, const int* in_sizes, int n_in,
                              void* d_out, int out_size) {
    XP xp;
    for (int t = 0; t < 4; t++) xp.x[t] = (const float*)d_in[t];
    const float* Wsrc = (const float*)d_in[4];
    const float* Wdst = (const float*)d_in[5];
    const float* asrc = (const float*)d_in[6];
    const float* adst = (const float*)d_in[7];
    const float* bias = (const float*)d_in[8];
    const float* lw   = (const float*)d_in[9];
    const float* lb   = (const float*)d_in[10];
    EP ep;
    for (int r = 0; r < 9; r++) {
        ep.s[r] = (const int*)d_in[11 + 2 * r];
        ep.d[r] = (const int*)d_in[12 + 2 * r];
    }
    const int* bvar = (const int*)d_in[29];
    const int* bcon = (const int*)d_in[30];

    // CSR build (edges are constant; rebuilt identically every call)
    csr_zero<<<(NDSUM + 255) / 256, 256>>>();
    csr_hist<<<(ETOT + 255) / 256, 256>>>(ep);
    csr_assign<<<(NDSUM + 255) / 256, 256>>>();
    csr_fill<<<(ETOT + 255) / 256, 256>>>(ep);
    prep<<<18, 128>>>(Wsrc, asrc, Wdst, adst);

    for (int l = 0; l < 2; l++) {
        const float* Ws_l = Wsrc + (size_t)l * 9 * 4096;
        const float* b_l  = bias + (size_t)l * 9 * 64;
        alpha_all<<<(NTOT + 31) / 32, 256>>>(xp, l, l * 9 * 64);
        fused<<<FUSED_BLK, 256>>>(Ws_l, b_l, l);
    }
    pool_kernel<<<((N0 + NPW - 1) / NPW + (N3 + NPW - 1) / NPW + 7) / 8, 256>>>(bvar, bcon);
    final_kernel<<<1, 128>>>(lw, lb, (float*)d_out);
}

// round 16
// speedup vs baseline: 1.0725x; 1.0725x over previous
#include <cuda_runtime.h>
#include <cuda_fp16.h>

#define H      64
#define E_PER  300000
#define RTOT   9
#define ETOT   (RTOT * E_PER)
#define NB     64
#define N0     100000
#define N1     20000
#define N2     50000
#define N3     80000
#define NTOT   250000
#define NMAX   100000
#define NDSUM  660000   // sum of Nd over relations

// ---------------- static device scratch ----------------
__device__ float   g_feat0[NTOT * H];
__device__ float   g_feat1[NTOT * H];
__device__ __half2 g_xh[(size_t)NTOT * 32];   // fp16 activated features (per layer)
__device__ float   g_als[RTOT * NMAX];
__device__ float   g_ald[RTOT * NMAX];
__device__ float   g_wsv[2 * RTOT * H];
__device__ float   g_wdv[2 * RTOT * H];
__device__ float   g_pool[NB * 2 * H];
__device__ float   g_cnt[2 * NB];
// compact CSR: entry index = c_DOFF[r] + d ; offsets are global into g_csrc
__device__ int     g_deg[NDSUM];
__device__ int     g_off[NDSUM];
__device__ int     g_cursor[1];
__device__ int     g_csrc[ETOT];
__device__ int     g_epos[ETOT];              // per-edge slot from hist pass

__constant__ int c_ST[9]  = {0, 0, 0, 2, 3, 1, 2, 3, 3};
__constant__ int c_NSZ[4] = {N0, N1, N2, N3};
__constant__ int c_OFF[4] = {0, N0, N0 + N1, N0 + N1 + N2};
__constant__ int c_DOFF[10] = {0, 20000, 70000, 150000, 230000, 310000,
                               410000, 510000, 610000, 660000};
// relations targeting type t, -1 padded
__constant__ int c_TB[4][3] = {{5, 6, 7}, {0, -1, -1}, {1, 8, -1}, {2, 3, 4}};
// cumulative 32-row tile counts per dst type
__constant__ int c_TILE0[5] = {0, 3125, 3750, 5313, 7813};
#define FUSED_BLK 7813
#define SG_STRIDE 66      // floats per sG row (bank-spread, 5 blocks/SM fit)
// per-type (relation,side) lists: code = (r<<1)|isDst
__constant__ int c_NSIDE[4]   = {6, 2, 4, 6};
__constant__ int c_SIDE[4][6] = {
    {0*2+0, 1*2+0, 2*2+0, 5*2+1, 6*2+1, 7*2+1},
    {5*2+0, 0*2+1, 0, 0, 0, 0},
    {3*2+0, 6*2+0, 1*2+1, 8*2+1, 0, 0},
    {4*2+0, 7*2+0, 8*2+0, 2*2+1, 3*2+1, 4*2+1},
};

struct XP { const float* x[4]; };
struct EP { const int* s[9]; const int* d[9]; };

// ---------------------------- tf32 helpers ----------------------------
__device__ __forceinline__ unsigned f2tf(float f) {
    unsigned u;
    asm("cvt.rna.tf32.f32 %0, %1;" : "=r"(u) : "f"(f));
    return u;
}
__device__ __forceinline__ void mma8(float* c, const unsigned* a, unsigned b0, unsigned b1) {
    asm volatile(
        "mma.sync.aligned.m16n8k8.row.col.f32.tf32.tf32.f32 "
        "{%0,%1,%2,%3},{%4,%5,%6,%7},{%8,%9},{%0,%1,%2,%3};"
        : "+f"(c[0]), "+f"(c[1]), "+f"(c[2]), "+f"(c[3])
        : "r"(a[0]), "r"(a[1]), "r"(a[2]), "r"(a[3]), "r"(b0), "r"(b1));
}

// fp16 row chunk (8 halves) weighted-accumulate into 8 fp32 accumulators
__device__ __forceinline__ void acc_h8(float* acc, float4 q, float pw) {
    __half2* h = (__half2*)&q;
    #pragma unroll
    for (int j = 0; j < 4; j++) {
        float2 f = __half22float2(h[j]);
        acc[2 * j]     += pw * f.x;
        acc[2 * j + 1] += pw * f.y;
    }
}

// ------------------------------- CSR build (once) -------------------------------
__global__ void csr_zero() {
    int i = blockIdx.x * blockDim.x + threadIdx.x;
    if (i < NDSUM) g_deg[i] = 0;
    if (i == 0)    g_cursor[0] = 0;
    if (i < NB * 2 * H) g_pool[i] = 0.f;       // fused pool_zero
    if (i < 2 * NB)     g_cnt[i]  = 0.f;
}

// histogram; also records each edge's slot within its dst list
__global__ void csr_hist(EP ep) {
    int idx = blockIdx.x * blockDim.x + threadIdx.x;
    if (idx >= ETOT) return;
    int r = idx / E_PER, e = idx - r * E_PER;
    int gi = c_DOFF[r] + __ldg(&ep.d[r][e]);
    g_epos[idx] = atomicAdd(&g_deg[gi], 1);
}

// block-aggregated global offset assignment (one cursor; list order irrelevant)
__global__ void csr_assign() {
    int i = blockIdx.x * 256 + threadIdx.x;
    int lane = threadIdx.x & 31, w = threadIdx.x >> 5;
    __shared__ int sm[8];
    int deg = (i < NDSUM) ? g_deg[i] : 0;
    int v = deg;
    #pragma unroll
    for (int o = 1; o < 32; o <<= 1) {
        int t = __shfl_up_sync(0xffffffffu, v, o);
        if (lane >= o) v += t;
    }
    if (lane == 31) sm[w] = v;
    __syncthreads();
    if (threadIdx.x == 0) {
        int tmp[8];
        int s = 0;
        #pragma unroll
        for (int k = 0; k < 8; k++) { tmp[k] = s; s += sm[k]; }
        int b = atomicAdd(&g_cursor[0], s);
        #pragma unroll
        for (int k = 0; k < 8; k++) sm[k] = tmp[k] + b;
    }
    __syncthreads();
    if (i < NDSUM) g_off[i] = sm[w] + v - deg;
}

// atomic-free fill using precomputed slots
__global__ void csr_fill(EP ep) {
    int idx = blockIdx.x * blockDim.x + threadIdx.x;
    if (idx >= ETOT) return;
    int r = idx / E_PER, e = idx - r * E_PER;
    int gi = c_DOFF[r] + __ldg(&ep.d[r][e]);
    g_csrc[g_off[gi] + g_epos[idx]] = __ldg(&ep.s[r][e]);
}

// ---------------------------------- per-layer -----------------------------------

// both layers: block rl in [0,18): wsv[rl][k] = sum_j Wsrc[rl][k][j]*asrc[rl][j]
__global__ void prep(const float* __restrict__ Ws, const float* __restrict__ as_,
                     const float* __restrict__ Wd, const float* __restrict__ ad_) {
    int rl = blockIdx.x, t = threadIdx.x;
    const float* W; const float* a; float* o; int k;
    if (t < 64) { W = Ws + rl * 4096; a = as_ + rl * 64; o = g_wsv + rl * 64; k = t; }
    else        { W = Wd + rl * 4096; a = ad_ + rl * 64; o = g_wdv + rl * 64; k = t - 64; }
    float s = 0.f;
    #pragma unroll
    for (int j = 0; j < 64; j++) s += W[k * 64 + j] * a[j];
    o[k] = s;
}

// 8-lane group per node (4 nodes/warp): attention logits via per-type side table,
// plus fp16 conversion of the activated feature row into g_xh.
__global__ void __launch_bounds__(256) alpha_all(XP xp, int use_feat, int wbase) {
    int tid = threadIdx.x, warp = tid >> 5, lane = tid & 31;
    int grp = lane >> 3, lg = lane & 7;
    unsigned gmask = 0xFFu << (grp * 8);
    int gw = blockIdx.x * 32 + warp * 4 + grp;
    if (gw >= NTOT) return;                     // uniform within each 8-lane group
    int t = (gw < N0) ? 0 : (gw < N0 + N1) ? 1 : (gw < N0 + N1 + N2) ? 2 : 3;
    int li = gw - c_OFF[t];
    const float4* x4 = (const float4*)(use_feat ? (g_feat0 + (size_t)c_OFF[t] * H)
                                                : xp.x[t]);
    float4 q0 = x4[(size_t)li * 16 + lg * 2];
    float4 q1 = x4[(size_t)li * 16 + lg * 2 + 1];
    if (use_feat) {
        q0.x = fmaxf(q0.x, 0.f); q0.y = fmaxf(q0.y, 0.f);
        q0.z = fmaxf(q0.z, 0.f); q0.w = fmaxf(q0.w, 0.f);
        q1.x = fmaxf(q1.x, 0.f); q1.y = fmaxf(q1.y, 0.f);
        q1.z = fmaxf(q1.z, 0.f); q1.w = fmaxf(q1.w, 0.f);
    }
    // fp16 row cache: lane lg covers halves [lg*8, lg*8+8) = one 16B store
    __half2 hh[4];
    hh[0] = __floats2half2_rn(q0.x, q0.y);
    hh[1] = __floats2half2_rn(q0.z, q0.w);
    hh[2] = __floats2half2_rn(q1.x, q1.y);
    hh[3] = __floats2half2_rn(q1.z, q1.w);
    *(float4*)&g_xh[(size_t)gw * 32 + lg * 4] = *(float4*)hh;

    int ns = c_NSIDE[t];
    for (int i = 0; i < ns; i++) {
        int code = c_SIDE[t][i];
        int r = code >> 1;
        const float* w = ((code & 1) ? g_wdv : g_wsv) + wbase + r * 64 + lg * 8;
        float4 w0 = *(const float4*)w;
        float4 w1 = *(const float4*)(w + 4);
        float s = q0.x * w0.x + q0.y * w0.y + q0.z * w0.z + q0.w * w0.w
                + q1.x * w1.x + q1.y * w1.y + q1.z * w1.z + q1.w * w1.w;
        #pragma unroll
        for (int o = 4; o; o >>= 1) s += __shfl_xor_sync(gmask, s, o, 8);
        if (lg == 0) ((code & 1) ? g_ald : g_als)[r * NMAX + li] = s;
    }
}

// Fused gather + single-TF32 GEMM per dst-type tile of 32 rows.
// ALL relations gathered first (no barriers; each group owns its rows in 3 sG
// buffers) -> one barrier -> 3 MMA rounds. Straggler inflation paid once.
__global__ void __launch_bounds__(256, 5) fused(const float* __restrict__ Ws_l,
                                                const float* __restrict__ bias_l,
                                                int outbuf) {
    __shared__ unsigned sG[3 * 32 * SG_STRIDE];  // gathered rows per relation, tf32 bits
    __shared__ unsigned sW[64 * 72];             // weights, tf32 bits
    __shared__ float sBias[64];
    int bx = blockIdx.x;
    int t = 0;
    #pragma unroll
    for (int i = 1; i < 4; i++) if (bx >= c_TILE0[i]) t = i;
    int row0 = (bx - c_TILE0[t]) * 32;
    int Nd = c_NSZ[t];
    int tid = threadIdx.x, warp = tid >> 5, lane = tid & 31;
    int grp = lane >> 3, lg = lane & 7;
    unsigned gmask = 0xFFu << (grp * 8);
    int nl = warp * 4 + grp;
    int d = row0 + nl;
    bool act = d < Nd;

    if (tid < 64) {
        float s = 0.f;
        #pragma unroll
        for (int i = 0; i < 3; i++) {
            int r = c_TB[t][i];
            if (r >= 0) s += bias_l[r * 64 + tid];
        }
        sBias[tid] = s;
    }

    // ---- phase 1: gather all relations, no block barriers ----
    for (int ri = 0; ri < 3; ri++) {
        int r = c_TB[t][ri];
        if (r < 0) break;
        int st = c_ST[r];
        const char* xb = (const char*)(g_xh + (size_t)c_OFF[st] * 32);

        float ald = 0.f; int beg = 0, deg = 0;
        if (act) {
            int gi = c_DOFF[r] + d;
            ald = __ldg(&g_ald[(size_t)r * NMAX + d]);
            beg = __ldg(&g_off[gi]);
            deg = __ldg(&g_deg[gi]);
        }
        const int* sl = g_csrc + beg;
        const float* als = g_als + (size_t)r * NMAX;
        unsigned loff = (unsigned)(lg * 16);

        float accA[8] = {0.f, 0.f, 0.f, 0.f, 0.f, 0.f, 0.f, 0.f};
        float accB[8] = {0.f, 0.f, 0.f, 0.f, 0.f, 0.f, 0.f, 0.f};
        float zl = 0.f;
        for (int base = 0; base < deg; base += 8) {
            int n = min(8, deg - base);
            int sidx = 0; float p = 0.f;
            if (lg < n) {
                sidx = __ldg(&sl[base + lg]);
                float sc = __ldg(&als[sidx]) + ald;
                sc = sc > 0.f ? sc : 0.2f * sc;
                p = __expf(sc);
            }
            zl += p;
            int i = 0;
            for (; i + 2 <= n; i += 2) {
                int   s0 = __shfl_sync(gmask, sidx, i,     8);
                int   s1 = __shfl_sync(gmask, sidx, i + 1, 8);
                float p0 = __shfl_sync(gmask, p,    i,     8);
                float p1 = __shfl_sync(gmask, p,    i + 1, 8);
                float4 q0 = *(const float4*)(xb + (((unsigned)s0 << 7) + loff));
                float4 q1 = *(const float4*)(xb + (((unsigned)s1 << 7) + loff));
                acc_h8(accA, q0, p0);
                acc_h8(accB, q1, p1);
            }
            if (i < n) {
                int   s0 = __shfl_sync(gmask, sidx, i, 8);
                float p0 = __shfl_sync(gmask, p,    i, 8);
                float4 q0 = *(const float4*)(xb + (((unsigned)s0 << 7) + loff));
                acc_h8(accA, q0, p0);
            }
        }
        #pragma unroll
        for (int o = 4; o; o >>= 1) zl += __shfl_xor_sync(gmask, zl, o, 8);
        float inv = act ? __fdividef(1.f, zl + 1e-16f) : 0.f;
        unsigned* gr = sG + ri * (32 * SG_STRIDE) + nl * SG_STRIDE + lg * 8;
        #pragma unroll
        for (int j = 0; j < 8; j++) gr[j] = f2tf((accA[j] + accB[j]) * inv);
    }
    __syncthreads();    // all gathers visible; sW safe to fill

    // ---- phase 2: per-relation W load + MMA, register accumulation ----
    // 8-warp MMA layout: warp -> 16-row half x 16-col quarter
    int mrow = (warp & 1) * 16;
    int nh = warp >> 1;                 // 0..3
    int gid = lane >> 2, tig = lane & 3;
    float acc[2][4];
    #pragma unroll
    for (int n = 0; n < 2; n++)
        #pragma unroll
        for (int j = 0; j < 4; j++) acc[n][j] = 0.f;

    for (int ri = 0; ri < 3; ri++) {
        int r = c_TB[t][ri];
        if (r < 0) break;
        if (ri) __syncthreads();       // previous MMA done reading sW

        const float4* W4 = (const float4*)(Ws_l + (size_t)r * 4096);
        #pragma unroll
        for (int i = 0; i < 4; i++) {
            int idx = tid + i * 256;
            int rr = idx >> 4, c4 = idx & 15;
            float4 v = W4[idx];
            unsigned* dst = sW + rr * 72 + c4 * 4;
            dst[0] = f2tf(v.x); dst[1] = f2tf(v.y);
            dst[2] = f2tf(v.z); dst[3] = f2tf(v.w);
        }
        __syncthreads();

        const unsigned* sGr = sG + ri * (32 * SG_STRIDE);
        #pragma unroll
        for (int k0 = 0; k0 < 8; k0++) {
            unsigned a_[4];
            a_[0] = sGr[(mrow + gid)     * SG_STRIDE + k0 * 8 + tig];
            a_[1] = sGr[(mrow + gid + 8) * SG_STRIDE + k0 * 8 + tig];
            a_[2] = sGr[(mrow + gid)     * SG_STRIDE + k0 * 8 + tig + 4];
            a_[3] = sGr[(mrow + gid + 8) * SG_STRIDE + k0 * 8 + tig + 4];
            #pragma unroll
            for (int n0 = 0; n0 < 2; n0++) {
                int nc = nh * 16 + n0 * 8 + gid;
                unsigned b0 = sW[(k0 * 8 + tig)     * 72 + nc];
                unsigned b1 = sW[(k0 * 8 + tig + 4) * 72 + nc];
                mma8(acc[n0], a_, b0, b1);
            }
        }
    }

    // epilogue: acc + bias -> fp32 feature rows
    float* fb = ((outbuf == 0) ? g_feat0 : g_feat1) + (size_t)c_OFF[t] * H;
    int rr0 = row0 + mrow + gid;
    int rr1 = rr0 + 8;
    #pragma unroll
    for (int n0 = 0; n0 < 2; n0++) {
        int cc = nh * 16 + n0 * 8 + 2 * tig;
        float b0 = sBias[cc], b1 = sBias[cc + 1];
        if (rr0 < Nd) {
            float2* p = (float2*)(fb + (size_t)rr0 * H + cc);
            *p = make_float2(acc[n0][0] + b0, acc[n0][1] + b1);
        }
        if (rr1 < Nd) {
            float2* p = (float2*)(fb + (size_t)rr1 * H + cc);
            *p = make_float2(acc[n0][2] + b0, acc[n0][3] + b1);
        }
    }
}

// ---------------------------------- pooling -------------------------------------
#define NPW 16
__global__ void pool_kernel(const int* __restrict__ bvar, const int* __restrict__ bcon) {
    int warp = threadIdx.x >> 5, lane = threadIdx.x & 31;
    int gw = blockIdx.x * 8 + warp;
    const int nvw = (N0 + NPW - 1) / NPW;
    const int ncw = (N3 + NPW - 1) / NPW;
    if (gw < nvw) {
        int i0 = gw * NPW, i1 = min(N0, i0 + NPW);
        float a0 = 0.f, a1 = 0.f, cnt = 0.f;
        int curb = __ldg(&bvar[i0]);
        for (int i = i0; i < i1; i++) {
            int b = __ldg(&bvar[i]);
            if (b != curb) {
                atomicAdd(&g_pool[curb * 128 + lane], a0);
                atomicAdd(&g_pool[curb * 128 + 32 + lane], a1);
                if (lane == 0) atomicAdd(&g_cnt[curb], cnt);
                a0 = a1 = 0.f; cnt = 0.f; curb = b;
            }
            size_t base = (size_t)i * H;
            a0 += fmaxf(g_feat1[base + lane], 0.f);
            a1 += fmaxf(g_feat1[base + 32 + lane], 0.f);
            cnt += 1.f;
        }
        atomicAdd(&g_pool[curb * 128 + lane], a0);
        atomicAdd(&g_pool[curb * 128 + 32 + lane], a1);
        if (lane == 0) atomicAdd(&g_cnt[curb], cnt);
    } else if (gw < nvw + ncw) {
        int gj = gw - nvw;
        const float* xc = g_feat1 + (size_t)(N0 + N1 + N2) * H;
        int i0 = gj * NPW, i1 = min(N3, i0 + NPW);
        float a0 = 0.f, a1 = 0.f, cnt = 0.f;
        int curb = __ldg(&bcon[i0]);
        for (int i = i0; i < i1; i++) {
            int b = __ldg(&bcon[i]);
            if (b != curb) {
                atomicAdd(&g_pool[curb * 128 + 64 + lane], a0);
                atomicAdd(&g_pool[curb * 128 + 96 + lane], a1);
                if (lane == 0) atomicAdd(&g_cnt[NB + curb], cnt);
                a0 = a1 = 0.f; cnt = 0.f; curb = b;
            }
            size_t base = (size_t)i * H;
            a0 += fmaxf(xc[base + lane], 0.f);
            a1 += fmaxf(xc[base + 32 + lane], 0.f);
            cnt += 1.f;
        }
        atomicAdd(&g_pool[curb * 128 + 64 + lane], a0);
        atomicAdd(&g_pool[curb * 128 + 96 + lane], a1);
        if (lane == 0) atomicAdd(&g_cnt[NB + curb], cnt);
    }
}

__global__ void final_kernel(const float* __restrict__ lw, const float* __restrict__ lb,
                             float* __restrict__ out) {
    int t = threadIdx.x;
    if (t >= 128) return;
    int b = t >> 1, o = t & 1;
    float cv = fmaxf(g_cnt[b], 1.f);
    float cc = fmaxf(g_cnt[NB + b], 1.f);
    float s = lb[o];
    #pragma unroll
    for (int j = 0; j < H; j++) {
        s += (g_pool[b * 128 + j]      / cv) * lw[o * 128 + j];
        s += (g_pool[b * 128 + 64 + j] / cc) * lw[o * 128 + 64 + j];
    }
    out[b * 2 + o] = s;
}

// ---------------------------------- launcher -------------------------------------
extern "C" void kernel_launch(void* const* d_in, const int* in_sizes, int n_in,
                              void* d_out, int out_size) {
    XP xp;
    for (int t = 0; t < 4; t++) xp.x[t] = (const float*)d_in[t];
    const float* Wsrc = (const float*)d_in[4];
    const float* Wdst = (const float*)d_in[5];
    const float* asrc = (const float*)d_in[6];
    const float* adst = (const float*)d_in[7];
    const float* bias = (const float*)d_in[8];
    const float* lw   = (const float*)d_in[9];
    const float* lb   = (const float*)d_in[10];
    EP ep;
    for (int r = 0; r < 9; r++) {
        ep.s[r] = (const int*)d_in[11 + 2 * r];
        ep.d[r] = (const int*)d_in[12 + 2 * r];
    }
    const int* bvar = (const int*)d_in[29];
    const int* bcon = (const int*)d_in[30];

    // CSR build (edges are constant; rebuilt identically every call)
    csr_zero<<<(NDSUM + 255) / 256, 256>>>();
    csr_hist<<<(ETOT + 255) / 256, 256>>>(ep);
    csr_assign<<<(NDSUM + 255) / 256, 256>>>();
    csr_fill<<<(ETOT + 255) / 256, 256>>>(ep);
    prep<<<18, 128>>>(Wsrc, asrc, Wdst, adst);

    for (int l = 0; l < 2; l++) {
        const float* Ws_l = Wsrc + (size_t)l * 9 * 4096;
        const float* b_l  = bias + (size_t)l * 9 * 64;
        alpha_all<<<(NTOT + 31) / 32, 256>>>(xp, l, l * 9 * 64);
        fused<<<FUSED_BLK, 256>>>(Ws_l, b_l, l);
    }
    pool_kernel<<<((N0 + NPW - 1) / NPW + (N3 + NPW - 1) / NPW + 7) / 8, 256>>>(bvar, bcon);
    final_kernel<<<1, 128>>>(lw, lb, (float*)d_out);
}